// round 6
// baseline (speedup 1.0000x reference)
#include <cuda_runtime.h>
#include <cuda_bf16.h>
#include <math.h>

#define TT 4096
#define EMB 512
#define HID 2048
#define NCH 256
#define NCOLS 8192            // 4*HID
#define NCTA 148              // co-resident CTAs (GB300 has 152 SMs)
#define BIGC 124              // CTAs 0..123 own 14 units, 124..147 own 13
#define MAXU 14
#define THR 448               // 14 warps
#define NSM 27                // weight rows cached in SMEM per CTA
#define G1C 13                // gate-1 rows cached for unit u < 13

// Static device scratch (allocation-free rule: __device__ globals only)
__device__ float g_Wt[(size_t)NCOLS * HID];     // Wt[gate*2048+j][k] = Wg[(512+k)*2048+j]
__device__ float g_Zx[(size_t)TT * NCOLS];      // input-part preactivations (+bias)
__device__ float g_hs[(size_t)TT * HID];        // hidden states per step
__device__ unsigned g_bar;

__device__ __forceinline__ unsigned ldacq(const unsigned* p) {
    unsigned v;
    asm volatile("ld.acquire.gpu.u32 %0, [%1];" : "=r"(v) : "l"(p) : "memory");
    return v;
}

__global__ void bar_init_kernel() { g_bar = 0u; }

// ---------------------------------------------------------------------------
// K0: transpose hidden-part of gate weights into row-per-output-column layout
// ---------------------------------------------------------------------------
__global__ __launch_bounds__(256) void wt_transpose_kernel(
    const float* __restrict__ W0, const float* __restrict__ W1,
    const float* __restrict__ W2, const float* __restrict__ W3)
{
    __shared__ float tile[32][33];
    int g = blockIdx.z;
    const float* W = (g == 0) ? W0 : (g == 1) ? W1 : (g == 2) ? W2 : W3;
    int k0 = blockIdx.x * 32;
    int j0 = blockIdx.y * 32;
    int tx = threadIdx.x & 31;
    int ty = threadIdx.x >> 5;

#pragma unroll
    for (int i = 0; i < 4; ++i) {
        int r = ty + i * 8;
        tile[r][tx] = W[(size_t)(EMB + k0 + r) * HID + (j0 + tx)];
    }
    __syncthreads();
#pragma unroll
    for (int i = 0; i < 4; ++i) {
        int r = ty + i * 8;
        g_Wt[((size_t)g * HID + (j0 + r)) * HID + (k0 + tx)] = tile[tx][r];
    }
}

// ---------------------------------------------------------------------------
// K1: Zx[t][g*2048+j] = emb[idx[t]] @ Wg[:512] + bg   (M=4096,N=8192,K=512)
// ---------------------------------------------------------------------------
__global__ __launch_bounds__(256) void zx_gemm_kernel(
    const int* __restrict__ idx, const float* __restrict__ emb,
    const float* __restrict__ W0, const float* __restrict__ W1,
    const float* __restrict__ W2, const float* __restrict__ W3,
    const float* __restrict__ b0, const float* __restrict__ b1,
    const float* __restrict__ b2, const float* __restrict__ b3)
{
    __shared__ float As[64][17];
    __shared__ float Bs[16][64];
    __shared__ int idx_s[64];

    int m0 = blockIdx.x * 64;
    int n0 = blockIdx.y * 64;
    int gate = n0 >> 11;
    int j0 = n0 & (HID - 1);
    const float* W = (gate == 0) ? W0 : (gate == 1) ? W1 : (gate == 2) ? W2 : W3;
    const float* bias = (gate == 0) ? b0 : (gate == 1) ? b1 : (gate == 2) ? b2 : b3;

    int tid = threadIdx.x;
    int tx = tid & 15, ty = tid >> 4;

    if (tid < 64) idx_s[tid] = idx[m0 + tid];
    __syncthreads();

    float acc[4][4] = {};
    for (int k0 = 0; k0 < EMB; k0 += 16) {
        {
            int kk = tid & 15;
            int mmb = tid >> 4;
#pragma unroll
            for (int r = 0; r < 4; ++r) {
                int mm = mmb + r * 16;
                As[mm][kk] = emb[(size_t)idx_s[mm] * EMB + k0 + kk];
            }
        }
        {
            int nn = tid & 63;
            int kkb = tid >> 6;
#pragma unroll
            for (int r = 0; r < 4; ++r) {
                int kk = kkb + r * 4;
                Bs[kk][nn] = W[(size_t)(k0 + kk) * HID + j0 + nn];
            }
        }
        __syncthreads();
#pragma unroll
        for (int kk = 0; kk < 16; ++kk) {
            float a[4];
#pragma unroll
            for (int i = 0; i < 4; ++i) a[i] = As[ty * 4 + i][kk];
            float4 bv = *(const float4*)&Bs[kk][tx * 4];
            float b[4] = {bv.x, bv.y, bv.z, bv.w};
#pragma unroll
            for (int i = 0; i < 4; ++i)
#pragma unroll
                for (int j = 0; j < 4; ++j) acc[i][j] += a[i] * b[j];
        }
        __syncthreads();
    }
#pragma unroll
    for (int i = 0; i < 4; ++i) {
        int m = m0 + ty * 4 + i;
#pragma unroll
        for (int j = 0; j < 4; ++j) {
            int n = n0 + tx * 4 + j;
            g_Zx[(size_t)m * NCOLS + n] = acc[i][j] + bias[j0 + tx * 4 + j];
        }
    }
}

// ---------------------------------------------------------------------------
// K2: persistent recurrent LSTM. 148 CTAs (one per SM), 448 threads (14 warps,
// up to 144 regs). CTA c owns 14 units (c<124) or 13 (c>=124); warp w = unit.
// Gate-3 row pinned in registers (64 regs). SMEM: gate-0 rows (<=14) +
// gate-1 rows for units 0..12 (<=27 rows total). Streamed LDG: gate-2 (all)
// + gate-1 of unit 13 (only in 14-unit CTAs), depth-2 software prefetch.
// Zx for t+1 loaded in the barrier shadow. All warps poll the atomic flag.
// ---------------------------------------------------------------------------
#define SMEM_FLOATS (HID + NSM * HID)
#define SMEM_BYTES (SMEM_FLOATS * 4)

__global__ __launch_bounds__(THR, 1) void lstm_seq_kernel(
    const float* __restrict__ hidden0, const float* __restrict__ cell0,
    float* __restrict__ dout)
{
    extern __shared__ float smem[];
    float* h_sh = smem;                 // [2048]
    float* wc   = smem + HID;           // [NSM][2048]

    const int cta  = blockIdx.x;
    const int tid  = threadIdx.x;
    const int w    = tid >> 5;          // warp = unit index within CTA
    const int lane = tid & 31;
    const int myUnits = (cta < BIGC) ? 14 : 13;
    const int hid0 = (cta < BIGC) ? cta * 14 : BIGC * 14 + (cta - BIGC) * 13;
    const bool active = (w < myUnits);

    // fill SMEM weight cache: slot u = gate0 row of unit u (u<myUnits);
    // slot 14+u = gate1 row of unit u (u<13)
    for (int slot = 0; slot < NSM; ++slot) {
        int gate = (slot < MAXU) ? 0 : 1;
        int u    = (slot < MAXU) ? slot : (slot - MAXU);
        bool valid = (gate == 0) ? (u < myUnits) : (u < G1C && u < myUnits);
        if (!valid) continue;
        const float* src = g_Wt + ((size_t)gate * HID + hid0 + u) * HID;
        for (int k = tid; k < HID; k += THR) wc[slot * HID + k] = src[k];
    }

    // pin gate-3 row slice in registers: 16 float4 (64 regs)
    float4 w3r[16];
    if (active) {
        const float4* w3g = (const float4*)(g_Wt + ((size_t)3 * HID + hid0 + w) * HID);
#pragma unroll
        for (int i = 0; i < 16; ++i) w3r[i] = w3g[i * 32 + lane];
    }

    float c = 0.f;
    if (active && lane == 0) c = cell0[hid0 + w];
    __syncthreads();

    const bool g1_smem = (w < G1C);
    const float4* p0 = (const float4*)(wc + w * HID);
    const float4* p1 = g1_smem
        ? (const float4*)(wc + (MAXU + w) * HID)
        : (const float4*)(g_Wt + ((size_t)1 * HID + hid0 + w) * HID);
    const float4* p2 = (const float4*)(g_Wt + ((size_t)2 * HID + hid0 + w) * HID);
    const float4* h4 = (const float4*)h_sh;
    float4* h4s = (float4*)h_sh;

    // Zx pipeline: preload step 0
    float zx0 = 0.f, zx1 = 0.f, zx2 = 0.f, zx3 = 0.f;
    if (active && lane == 0) {
        const float* zp = g_Zx + hid0 + w;
        zx0 = zp[0]; zx1 = zp[HID]; zx2 = zp[2 * HID]; zx3 = zp[3 * HID];
    }

    for (int t = 0; t < TT; ++t) {
        // stage h_{t-1} into SMEM (512 float4 over 448 threads)
        const float4* hprev4 = (t == 0)
            ? (const float4*)hidden0
            : (const float4*)(g_hs + (size_t)(t - 1) * HID);
        for (int i = tid; i < 512; i += THR) h4s[i] = hprev4[i];
        __syncthreads();

        if (active) {
            // matvec: 4 gate rows of unit w; gate-2 LDG with depth-2 prefetch
            float4 v2c = __ldg(p2 + lane);
            float4 v2n = __ldg(p2 + 32 + lane);
            float a0 = 0.f, a1 = 0.f, a2 = 0.f, a3 = 0.f;
            float b0 = 0.f, b1 = 0.f, b2 = 0.f, b3 = 0.f;
#pragma unroll
            for (int i = 0; i < 16; ++i) {
                int i4 = i * 32 + lane;
                float4 v2 = v2c;
                v2c = v2n;
                if (i + 2 < 16) v2n = __ldg(p2 + (i + 2) * 32 + lane);
                float4 v1 = g1_smem ? p1[i4] : __ldg(p1 + i4);
                float4 v0 = p0[i4];
                float4 hv = h4[i4];
                float4 w3 = w3r[i];
                a0 += v0.x * hv.x + v0.y * hv.y;
                b0 += v0.z * hv.z + v0.w * hv.w;
                a1 += v1.x * hv.x + v1.y * hv.y;
                b1 += v1.z * hv.z + v1.w * hv.w;
                a2 += v2.x * hv.x + v2.y * hv.y;
                b2 += v2.z * hv.z + v2.w * hv.w;
                a3 += w3.x * hv.x + w3.y * hv.y;
                b3 += w3.z * hv.z + w3.w * hv.w;
            }
            float s0 = a0 + b0, s1 = a1 + b1, s2 = a2 + b2, s3 = a3 + b3;
#pragma unroll
            for (int off = 16; off; off >>= 1) {
                s0 += __shfl_down_sync(0xffffffffu, s0, off);
                s1 += __shfl_down_sync(0xffffffffu, s1, off);
                s2 += __shfl_down_sync(0xffffffffu, s2, off);
                s3 += __shfl_down_sync(0xffffffffu, s3, off);
            }

            if (lane == 0) {
                float zf = s0 + zx0;
                float zi = s1 + zx1;
                float zo = s2 + zx2;
                float zc = s3 + zx3;
                float f  = 1.0f / (1.0f + __expf(-zf));
                float i_ = 1.0f / (1.0f + __expf(-zi));
                float o_ = 1.0f / (1.0f + __expf(-zo));
                float gg = tanhf(zc);
                c = f * c + i_ * gg;
                float hn = o_ * tanhf(c);
                g_hs[(size_t)t * HID + hid0 + w] = hn;
                if (t == TT - 1) {
                    dout[(size_t)TT * NCH + hid0 + w] = hn;          // h_fin
                    dout[(size_t)TT * NCH + HID + hid0 + w] = c;     // c_fin
                }
            }
        }
        __syncthreads();

        // release (orders h stores after the bar), prefetch Zx(t+1) in the
        // barrier shadow, then ALL warps poll the single atomic counter
        if (tid == 0) {
            asm volatile("red.release.gpu.global.add.u32 [%0], %1;"
                         :: "l"(&g_bar), "r"(1u) : "memory");
        }
        {
            int tn = (t + 1 < TT) ? (t + 1) : t;
            if (active && lane == 0) {
                const float* zp = g_Zx + (size_t)tn * NCOLS + hid0 + w;
                zx0 = zp[0]; zx1 = zp[HID]; zx2 = zp[2 * HID]; zx3 = zp[3 * HID];
            }
        }
        {
            unsigned target = (unsigned)(t + 1) * (unsigned)NCTA;
            while (ldacq(&g_bar) < target) { }
        }
        // no trailing __syncthreads: each warp proceeds to stage h for t+1;
        // the __syncthreads after staging orders h_sh writes vs reads
    }
}

// ---------------------------------------------------------------------------
// K3: out[t][n] = hs[t] @ Wout + bout.  M=4096, N=256, K=2048
// ---------------------------------------------------------------------------
__global__ __launch_bounds__(256) void out_gemm_kernel(
    const float* __restrict__ Wout, const float* __restrict__ bout,
    float* __restrict__ dout)
{
    __shared__ float As[64][17];
    __shared__ float Bs[16][64];

    int m0 = blockIdx.x * 64;
    int n0 = blockIdx.y * 64;
    int tid = threadIdx.x;
    int tx = tid & 15, ty = tid >> 4;

    float acc[4][4] = {};
    for (int k0 = 0; k0 < HID; k0 += 16) {
        {
            int kk = tid & 15;
            int mmb = tid >> 4;
#pragma unroll
            for (int r = 0; r < 4; ++r) {
                int mm = mmb + r * 16;
                As[mm][kk] = g_hs[(size_t)(m0 + mm) * HID + k0 + kk];
            }
        }
        {
            int nn = tid & 63;
            int kkb = tid >> 6;
#pragma unroll
            for (int r = 0; r < 4; ++r) {
                int kk = kkb + r * 4;
                Bs[kk][nn] = Wout[(size_t)(k0 + kk) * NCH + n0 + nn];
            }
        }
        __syncthreads();
#pragma unroll
        for (int kk = 0; kk < 16; ++kk) {
            float a[4];
#pragma unroll
            for (int i = 0; i < 4; ++i) a[i] = As[ty * 4 + i][kk];
            float4 bv = *(const float4*)&Bs[kk][tx * 4];
            float b[4] = {bv.x, bv.y, bv.z, bv.w};
#pragma unroll
            for (int i = 0; i < 4; ++i)
#pragma unroll
                for (int j = 0; j < 4; ++j) acc[i][j] += a[i] * b[j];
        }
        __syncthreads();
    }
#pragma unroll
    for (int i = 0; i < 4; ++i) {
        int m = m0 + ty * 4 + i;
#pragma unroll
        for (int j = 0; j < 4; ++j) {
            int n = n0 + tx * 4 + j;
            dout[(size_t)m * NCH + n] = acc[i][j] + bout[n];
        }
    }
}

// ---------------------------------------------------------------------------
extern "C" void kernel_launch(void* const* d_in, const int* in_sizes, int n_in,
                              void* d_out, int out_size)
{
    const int*   idx    = (const int*)d_in[0];
    const float* hidden = (const float*)d_in[1];
    const float* cell   = (const float*)d_in[2];
    const float* emb    = (const float*)d_in[3];
    const float* Wf     = (const float*)d_in[4];
    const float* bf     = (const float*)d_in[5];
    const float* Wi     = (const float*)d_in[6];
    const float* bi     = (const float*)d_in[7];
    const float* Wo     = (const float*)d_in[8];
    const float* bo     = (const float*)d_in[9];
    const float* Wc     = (const float*)d_in[10];
    const float* bc     = (const float*)d_in[11];
    const float* Wout   = (const float*)d_in[12];
    const float* bout   = (const float*)d_in[13];
    float* out = (float*)d_out;

    cudaFuncSetAttribute(lstm_seq_kernel,
                         cudaFuncAttributeMaxDynamicSharedMemorySize, SMEM_BYTES);

    bar_init_kernel<<<1, 1>>>();
    wt_transpose_kernel<<<dim3(64, 64, 4), 256>>>(Wf, Wi, Wo, Wc);
    zx_gemm_kernel<<<dim3(64, 128), 256>>>(idx, emb, Wf, Wi, Wo, Wc, bf, bi, bo, bc);
    lstm_seq_kernel<<<NCTA, THR, SMEM_BYTES>>>(hidden, cell, out);
    out_gemm_kernel<<<dim3(64, 4), 256>>>(Wout, bout, out);
}

// round 7
// speedup vs baseline: 1.1522x; 1.1522x over previous
#include <cuda_runtime.h>
#include <cuda_bf16.h>
#include <math.h>

#define TT 4096
#define EMB 512
#define HID 2048
#define NCH 256
#define NCOLS 8192            // 4*HID
#define NCTA 128
#define HPB 16                // hidden units per CTA (2 warps each)
#define THR 1024              // 32 warps
#define NSM 27                // weight rows cached in SMEM per CTA (of 64)
#define G1S 11                // gate-1 rows in SMEM for unit u < G1S

// Static device scratch (allocation-free rule: __device__ globals only)
__device__ float g_Wt[(size_t)NCOLS * HID];     // Wt[gate*2048+j][k] = Wg[(512+k)*2048+j]
__device__ float g_Zx[(size_t)TT * NCOLS];      // input-part preactivations (+bias)
__device__ float g_hs[(size_t)TT * HID];        // hidden states per step
__device__ unsigned g_bar;

__device__ __forceinline__ unsigned ldacq(const unsigned* p) {
    unsigned v;
    asm volatile("ld.acquire.gpu.u32 %0, [%1];" : "=r"(v) : "l"(p) : "memory");
    return v;
}

__global__ void bar_init_kernel() { g_bar = 0u; }

// ---------------------------------------------------------------------------
// K0: transpose hidden-part of gate weights into row-per-output-column layout
// ---------------------------------------------------------------------------
__global__ __launch_bounds__(256) void wt_transpose_kernel(
    const float* __restrict__ W0, const float* __restrict__ W1,
    const float* __restrict__ W2, const float* __restrict__ W3)
{
    __shared__ float tile[32][33];
    int g = blockIdx.z;
    const float* W = (g == 0) ? W0 : (g == 1) ? W1 : (g == 2) ? W2 : W3;
    int k0 = blockIdx.x * 32;
    int j0 = blockIdx.y * 32;
    int tx = threadIdx.x & 31;
    int ty = threadIdx.x >> 5;

#pragma unroll
    for (int i = 0; i < 4; ++i) {
        int r = ty + i * 8;
        tile[r][tx] = W[(size_t)(EMB + k0 + r) * HID + (j0 + tx)];
    }
    __syncthreads();
#pragma unroll
    for (int i = 0; i < 4; ++i) {
        int r = ty + i * 8;
        g_Wt[((size_t)g * HID + (j0 + r)) * HID + (k0 + tx)] = tile[tx][r];
    }
}

// ---------------------------------------------------------------------------
// K1: Zx[t][g*2048+j] = emb[idx[t]] @ Wg[:512] + bg   (M=4096,N=8192,K=512)
// ---------------------------------------------------------------------------
__global__ __launch_bounds__(256) void zx_gemm_kernel(
    const int* __restrict__ idx, const float* __restrict__ emb,
    const float* __restrict__ W0, const float* __restrict__ W1,
    const float* __restrict__ W2, const float* __restrict__ W3,
    const float* __restrict__ b0, const float* __restrict__ b1,
    const float* __restrict__ b2, const float* __restrict__ b3)
{
    __shared__ float As[64][17];
    __shared__ float Bs[16][64];
    __shared__ int idx_s[64];

    int m0 = blockIdx.x * 64;
    int n0 = blockIdx.y * 64;
    int gate = n0 >> 11;
    int j0 = n0 & (HID - 1);
    const float* W = (gate == 0) ? W0 : (gate == 1) ? W1 : (gate == 2) ? W2 : W3;
    const float* bias = (gate == 0) ? b0 : (gate == 1) ? b1 : (gate == 2) ? b2 : b3;

    int tid = threadIdx.x;
    int tx = tid & 15, ty = tid >> 4;

    if (tid < 64) idx_s[tid] = idx[m0 + tid];
    __syncthreads();

    float acc[4][4] = {};
    for (int k0 = 0; k0 < EMB; k0 += 16) {
        {
            int kk = tid & 15;
            int mmb = tid >> 4;
#pragma unroll
            for (int r = 0; r < 4; ++r) {
                int mm = mmb + r * 16;
                As[mm][kk] = emb[(size_t)idx_s[mm] * EMB + k0 + kk];
            }
        }
        {
            int nn = tid & 63;
            int kkb = tid >> 6;
#pragma unroll
            for (int r = 0; r < 4; ++r) {
                int kk = kkb + r * 4;
                Bs[kk][nn] = W[(size_t)(k0 + kk) * HID + j0 + nn];
            }
        }
        __syncthreads();
#pragma unroll
        for (int kk = 0; kk < 16; ++kk) {
            float a[4];
#pragma unroll
            for (int i = 0; i < 4; ++i) a[i] = As[ty * 4 + i][kk];
            float4 bv = *(const float4*)&Bs[kk][tx * 4];
            float b[4] = {bv.x, bv.y, bv.z, bv.w};
#pragma unroll
            for (int i = 0; i < 4; ++i)
#pragma unroll
                for (int j = 0; j < 4; ++j) acc[i][j] += a[i] * b[j];
        }
        __syncthreads();
    }
#pragma unroll
    for (int i = 0; i < 4; ++i) {
        int m = m0 + ty * 4 + i;
#pragma unroll
        for (int j = 0; j < 4; ++j) {
            int n = n0 + tx * 4 + j;
            g_Zx[(size_t)m * NCOLS + n] = acc[i][j] + bias[j0 + tx * 4 + j];
        }
    }
}

// ---------------------------------------------------------------------------
// K2: persistent recurrent LSTM, split-K two-warps-per-unit.
// 128 CTAs x 1024 threads (32 warps, 8/SMSP, <=64 regs).
// Unit u = w>>1; half = w&1 selects k in [half*1024, half*1024+1024).
// Each warp: 4 gate rows of its unit over its k-half (8 float4 iters).
// Gate-3 half-row pinned in registers (32 regs). SMEM: gate-0 all 16 units
// + gate-1 units 0..10 (27 rows). Streamed LDG: gate-2 + gate-1 units 11..15.
// Odd warp writes 4 partials to SMEM; even warp lane0 combines + gate math.
// Same l1tex traffic as R3 but 2x warps to hide latency.
// ---------------------------------------------------------------------------
#define SMEM_FLOATS (HID + NSM * HID + 64)
#define SMEM_BYTES (SMEM_FLOATS * 4)

__global__ __launch_bounds__(THR, 1) void lstm_seq_kernel(
    const float* __restrict__ hidden0, const float* __restrict__ cell0,
    float* __restrict__ dout)
{
    extern __shared__ float smem[];
    float* h_sh  = smem;                 // [2048]
    float* wc    = smem + HID;           // [NSM][2048]
    float* zpart = wc + NSM * HID;       // [16][4] odd-warp partials

    const int cta  = blockIdx.x;
    const int tid  = threadIdx.x;
    const int w    = tid >> 5;           // warp 0..31
    const int lane = tid & 31;
    const int u    = w >> 1;             // unit 0..15
    const int half = w & 1;              // k-half
    const int hid0 = cta * HPB;
    const int koff = half * 256;         // float4 offset of k-half

    // fill SMEM weight cache: slot u = gate0 row; slot 16+u = gate1 (u<11)
    for (int slot = 0; slot < NSM; ++slot) {
        int gate = (slot < 16) ? 0 : 1;
        int j    = (slot < 16) ? slot : (slot - 16);
        const float* src = g_Wt + ((size_t)gate * HID + hid0 + j) * HID;
        for (int k = tid; k < HID; k += THR) wc[slot * HID + k] = src[k];
    }

    // pin gate-3 half-row in registers: 8 float4 (32 regs)
    const float4* w3g = (const float4*)(g_Wt + ((size_t)3 * HID + hid0 + u) * HID) + koff;
    float4 w3r[8];
#pragma unroll
    for (int i = 0; i < 8; ++i) w3r[i] = w3g[i * 32 + lane];

    // cell state: even-warp lane 0
    float c = 0.f;
    if (half == 0 && lane == 0) c = cell0[hid0 + u];
    __syncthreads();

    const bool g1_smem = (u < G1S);
    const float4* p0 = (const float4*)(wc + u * HID) + koff;
    const float4* p1 = (g1_smem
        ? (const float4*)(wc + (16 + u) * HID)
        : (const float4*)(g_Wt + ((size_t)1 * HID + hid0 + u) * HID)) + koff;
    const float4* p2 = (const float4*)(g_Wt + ((size_t)2 * HID + hid0 + u) * HID) + koff;
    const float4* h4 = (const float4*)h_sh + koff;
    float4* h4s = (float4*)h_sh;

    for (int t = 0; t < TT; ++t) {
        // Zx prefetch (independent of h), even-warp lane0 only
        float zx0 = 0.f, zx1 = 0.f, zx2 = 0.f, zx3 = 0.f;
        if (half == 0 && lane == 0) {
            const float* zp = g_Zx + (size_t)t * NCOLS + hid0 + u;
            zx0 = zp[0];
            zx1 = zp[HID];
            zx2 = zp[2 * HID];
            zx3 = zp[3 * HID];
        }

        // stage h_{t-1} into SMEM (512 float4, threads 0..511)
        const float4* hprev4 = (t == 0)
            ? (const float4*)hidden0
            : (const float4*)(g_hs + (size_t)(t - 1) * HID);
        if (tid < 512) h4s[tid] = hprev4[tid];
        __syncthreads();

        // matvec over this warp's k-half: 4 gate rows of unit u
        float s0 = 0.f, s1 = 0.f, s2 = 0.f, s3 = 0.f;
#pragma unroll
        for (int i = 0; i < 8; ++i) {
            int i4 = i * 32 + lane;
            float4 v2 = __ldg(p2 + i4);                       // LDG (L2)
            float4 v1 = g1_smem ? p1[i4] : __ldg(p1 + i4);    // LDS/LDG
            float4 v0 = p0[i4];                               // LDS
            float4 hv = h4[i4];                               // LDS
            float4 w3 = w3r[i];
            s0 += v0.x * hv.x + v0.y * hv.y + v0.z * hv.z + v0.w * hv.w;
            s1 += v1.x * hv.x + v1.y * hv.y + v1.z * hv.z + v1.w * hv.w;
            s2 += v2.x * hv.x + v2.y * hv.y + v2.z * hv.z + v2.w * hv.w;
            s3 += w3.x * hv.x + w3.y * hv.y + w3.z * hv.z + w3.w * hv.w;
        }
#pragma unroll
        for (int off = 16; off; off >>= 1) {
            s0 += __shfl_down_sync(0xffffffffu, s0, off);
            s1 += __shfl_down_sync(0xffffffffu, s1, off);
            s2 += __shfl_down_sync(0xffffffffu, s2, off);
            s3 += __shfl_down_sync(0xffffffffu, s3, off);
        }

        // odd warp publishes partials; even warp keeps its own in regs
        if (half == 1 && lane == 0) {
            float* zb = zpart + u * 4;
            zb[0] = s0; zb[1] = s1; zb[2] = s2; zb[3] = s3;
        }
        __syncthreads();

        // even-warp lane0: combine halves, gate math, store h
        if (half == 0 && lane == 0) {
            const float* zb = zpart + u * 4;
            float zf = s0 + zb[0] + zx0;
            float zi = s1 + zb[1] + zx1;
            float zo = s2 + zb[2] + zx2;
            float zc = s3 + zb[3] + zx3;
            float f  = 1.0f / (1.0f + __expf(-zf));
            float i_ = 1.0f / (1.0f + __expf(-zi));
            float o_ = 1.0f / (1.0f + __expf(-zo));
            float gg = tanhf(zc);
            c = f * c + i_ * gg;
            float hn = o_ * tanhf(c);
            g_hs[(size_t)t * HID + hid0 + u] = hn;
            if (t == TT - 1) {
                dout[(size_t)TT * NCH + hid0 + u] = hn;          // h_fin
                dout[(size_t)TT * NCH + HID + hid0 + u] = c;     // c_fin
            }
        }
        __syncthreads();

        // grid barrier (128 CTAs co-resident, 1/SM) — R3-proven form
        if (tid == 0) {
            asm volatile("red.release.gpu.global.add.u32 [%0], %1;"
                         :: "l"(&g_bar), "r"(1u) : "memory");
            unsigned target = (unsigned)(t + 1) * gridDim.x;
            while (ldacq(&g_bar) < target) { }
        }
        __syncthreads();
    }
}

// ---------------------------------------------------------------------------
// K3: out[t][n] = hs[t] @ Wout + bout.  M=4096, N=256, K=2048
// ---------------------------------------------------------------------------
__global__ __launch_bounds__(256) void out_gemm_kernel(
    const float* __restrict__ Wout, const float* __restrict__ bout,
    float* __restrict__ dout)
{
    __shared__ float As[64][17];
    __shared__ float Bs[16][64];

    int m0 = blockIdx.x * 64;
    int n0 = blockIdx.y * 64;
    int tid = threadIdx.x;
    int tx = tid & 15, ty = tid >> 4;

    float acc[4][4] = {};
    for (int k0 = 0; k0 < HID; k0 += 16) {
        {
            int kk = tid & 15;
            int mmb = tid >> 4;
#pragma unroll
            for (int r = 0; r < 4; ++r) {
                int mm = mmb + r * 16;
                As[mm][kk] = g_hs[(size_t)(m0 + mm) * HID + k0 + kk];
            }
        }
        {
            int nn = tid & 63;
            int kkb = tid >> 6;
#pragma unroll
            for (int r = 0; r < 4; ++r) {
                int kk = kkb + r * 4;
                Bs[kk][nn] = Wout[(size_t)(k0 + kk) * NCH + n0 + nn];
            }
        }
        __syncthreads();
#pragma unroll
        for (int kk = 0; kk < 16; ++kk) {
            float a[4];
#pragma unroll
            for (int i = 0; i < 4; ++i) a[i] = As[ty * 4 + i][kk];
            float4 bv = *(const float4*)&Bs[kk][tx * 4];
            float b[4] = {bv.x, bv.y, bv.z, bv.w};
#pragma unroll
            for (int i = 0; i < 4; ++i)
#pragma unroll
                for (int j = 0; j < 4; ++j) acc[i][j] += a[i] * b[j];
        }
        __syncthreads();
    }
#pragma unroll
    for (int i = 0; i < 4; ++i) {
        int m = m0 + ty * 4 + i;
#pragma unroll
        for (int j = 0; j < 4; ++j) {
            int n = n0 + tx * 4 + j;
            dout[(size_t)m * NCH + n] = acc[i][j] + bout[n];
        }
    }
}

// ---------------------------------------------------------------------------
extern "C" void kernel_launch(void* const* d_in, const int* in_sizes, int n_in,
                              void* d_out, int out_size)
{
    const int*   idx    = (const int*)d_in[0];
    const float* hidden = (const float*)d_in[1];
    const float* cell   = (const float*)d_in[2];
    const float* emb    = (const float*)d_in[3];
    const float* Wf     = (const float*)d_in[4];
    const float* bf     = (const float*)d_in[5];
    const float* Wi     = (const float*)d_in[6];
    const float* bi     = (const float*)d_in[7];
    const float* Wo     = (const float*)d_in[8];
    const float* bo     = (const float*)d_in[9];
    const float* Wc     = (const float*)d_in[10];
    const float* bc     = (const float*)d_in[11];
    const float* Wout   = (const float*)d_in[12];
    const float* bout   = (const float*)d_in[13];
    float* out = (float*)d_out;

    cudaFuncSetAttribute(lstm_seq_kernel,
                         cudaFuncAttributeMaxDynamicSharedMemorySize, SMEM_BYTES);

    bar_init_kernel<<<1, 1>>>();
    wt_transpose_kernel<<<dim3(64, 64, 4), 256>>>(Wf, Wi, Wo, Wc);
    zx_gemm_kernel<<<dim3(64, 128), 256>>>(idx, emb, Wf, Wi, Wo, Wc, bf, bi, bo, bc);
    lstm_seq_kernel<<<NCTA, THR, SMEM_BYTES>>>(hidden, cell, out);
    out_gemm_kernel<<<dim3(64, 4), 256>>>(Wout, bout, out);
}

// round 8
// speedup vs baseline: 1.6455x; 1.4281x over previous
#include <cuda_runtime.h>
#include <cuda_fp16.h>
#include <math.h>

#define TT 4096
#define EMB 512
#define HID 2048
#define NCH 256
#define NCOLS 8192            // 4*HID
#define NCTA 128
#define HPB 16                // hidden units per CTA (one warp each)
#define THR 512               // 16 warps
#define NSM 48                // fp16 weight rows in SMEM per CTA (gates 0,1,2)

// Static device scratch (allocation-free rule: __device__ globals only)
__device__ __half g_Wth[(size_t)NCOLS * HID];   // fp16 Wt[gate*2048+j][k] = Wg[(512+k)*2048+j]
__device__ float  g_Zx[(size_t)TT * NCOLS];     // input-part preactivations (+bias), fp32
__device__ float  g_hs[(size_t)TT * HID];       // hidden states per step, fp32
__device__ unsigned g_bar;

__device__ __forceinline__ unsigned ldacq(const unsigned* p) {
    unsigned v;
    asm volatile("ld.acquire.gpu.u32 %0, [%1];" : "=r"(v) : "l"(p) : "memory");
    return v;
}

__global__ void bar_init_kernel() { g_bar = 0u; }

// ---------------------------------------------------------------------------
// K0: transpose hidden-part of gate weights into row-per-output-column layout,
//     converting to fp16 (weights are N(0, 0.02^2): far inside fp16 range)
// ---------------------------------------------------------------------------
__global__ __launch_bounds__(256) void wt_transpose_kernel(
    const float* __restrict__ W0, const float* __restrict__ W1,
    const float* __restrict__ W2, const float* __restrict__ W3)
{
    __shared__ float tile[32][33];
    int g = blockIdx.z;
    const float* W = (g == 0) ? W0 : (g == 1) ? W1 : (g == 2) ? W2 : W3;
    int k0 = blockIdx.x * 32;
    int j0 = blockIdx.y * 32;
    int tx = threadIdx.x & 31;
    int ty = threadIdx.x >> 5;

#pragma unroll
    for (int i = 0; i < 4; ++i) {
        int r = ty + i * 8;
        tile[r][tx] = W[(size_t)(EMB + k0 + r) * HID + (j0 + tx)];
    }
    __syncthreads();
#pragma unroll
    for (int i = 0; i < 4; ++i) {
        int r = ty + i * 8;
        g_Wth[((size_t)g * HID + (j0 + r)) * HID + (k0 + tx)] = __float2half(tile[tx][r]);
    }
}

// ---------------------------------------------------------------------------
// K1: Zx[t][g*2048+j] = emb[idx[t]] @ Wg[:512] + bg   (M=4096,N=8192,K=512)
//     fp32 throughout (input path precision preserved)
// ---------------------------------------------------------------------------
__global__ __launch_bounds__(256) void zx_gemm_kernel(
    const int* __restrict__ idx, const float* __restrict__ emb,
    const float* __restrict__ W0, const float* __restrict__ W1,
    const float* __restrict__ W2, const float* __restrict__ W3,
    const float* __restrict__ b0, const float* __restrict__ b1,
    const float* __restrict__ b2, const float* __restrict__ b3)
{
    __shared__ float As[64][17];
    __shared__ float Bs[16][64];
    __shared__ int idx_s[64];

    int m0 = blockIdx.x * 64;
    int n0 = blockIdx.y * 64;
    int gate = n0 >> 11;
    int j0 = n0 & (HID - 1);
    const float* W = (gate == 0) ? W0 : (gate == 1) ? W1 : (gate == 2) ? W2 : W3;
    const float* bias = (gate == 0) ? b0 : (gate == 1) ? b1 : (gate == 2) ? b2 : b3;

    int tid = threadIdx.x;
    int tx = tid & 15, ty = tid >> 4;

    if (tid < 64) idx_s[tid] = idx[m0 + tid];
    __syncthreads();

    float acc[4][4] = {};
    for (int k0 = 0; k0 < EMB; k0 += 16) {
        {
            int kk = tid & 15;
            int mmb = tid >> 4;
#pragma unroll
            for (int r = 0; r < 4; ++r) {
                int mm = mmb + r * 16;
                As[mm][kk] = emb[(size_t)idx_s[mm] * EMB + k0 + kk];
            }
        }
        {
            int nn = tid & 63;
            int kkb = tid >> 6;
#pragma unroll
            for (int r = 0; r < 4; ++r) {
                int kk = kkb + r * 4;
                Bs[kk][nn] = W[(size_t)(k0 + kk) * HID + j0 + nn];
            }
        }
        __syncthreads();
#pragma unroll
        for (int kk = 0; kk < 16; ++kk) {
            float a[4];
#pragma unroll
            for (int i = 0; i < 4; ++i) a[i] = As[ty * 4 + i][kk];
            float4 bv = *(const float4*)&Bs[kk][tx * 4];
            float b[4] = {bv.x, bv.y, bv.z, bv.w};
#pragma unroll
            for (int i = 0; i < 4; ++i)
#pragma unroll
                for (int j = 0; j < 4; ++j) acc[i][j] += a[i] * b[j];
        }
        __syncthreads();
    }
#pragma unroll
    for (int i = 0; i < 4; ++i) {
        int m = m0 + ty * 4 + i;
#pragma unroll
        for (int j = 0; j < 4; ++j) {
            int n = n0 + tx * 4 + j;
            g_Zx[(size_t)m * NCOLS + n] = acc[i][j] + bias[j0 + tx * 4 + j];
        }
    }
}

// ---------------------------------------------------------------------------
// K2: persistent recurrent LSTM — R3 skeleton, fp16 weights.
// 128 CTAs x 512 threads (16 warps). Warp w owns hidden unit hid0+w (4 gate
// rows). Lane l covers k chunks i*128+l*4. Weights fp16: gates 0,1,2 all in
// SMEM (48 rows x 4KB = 192KB + 8KB h = 200KB), gate-3 pinned in RF as fp16
// (uint2 x16 = 32 regs). NO streamed LDG in the mainloop. h stays fp32;
// fp16->fp32 cvt feeds fp32 FFMA, so only weight quantization error enters.
// Grid barrier: single release-atomic + tid0 poll (R3-proven).
// ---------------------------------------------------------------------------
#define SMEM_BYTES (HID * 4 + NSM * HID * 2)

__global__ __launch_bounds__(THR, 1) void lstm_seq_kernel(
    const float* __restrict__ hidden0, const float* __restrict__ cell0,
    float* __restrict__ dout)
{
    extern __shared__ float smem[];
    float*  h_sh = smem;                          // fp32 [2048]
    __half* wc   = (__half*)(smem + HID);         // fp16 [48][2048]

    const int cta  = blockIdx.x;
    const int tid  = threadIdx.x;
    const int w    = tid >> 5;          // warp = hidden unit index within CTA
    const int lane = tid & 31;
    const int hid0 = cta * HPB;

    // fill SMEM weight cache: slot = gate*16 + u, gates 0..2 (fp16 copy)
    for (int slot = 0; slot < NSM; ++slot) {
        int gate = slot >> 4;
        int u    = slot & 15;
        const __half* src = g_Wth + ((size_t)gate * HID + hid0 + u) * HID;
        uint2* dst4 = (uint2*)(wc + (size_t)slot * HID);
        const uint2* src4 = (const uint2*)src;
        for (int k = tid; k < HID / 4; k += THR) dst4[k] = src4[k];
    }

    // pin gate-3 row in registers as fp16: 16 x uint2 (4 halves each) = 32 regs
    const uint2* w3g = (const uint2*)(g_Wth + ((size_t)3 * HID + hid0 + w) * HID);
    uint2 w3r[16];
#pragma unroll
    for (int i = 0; i < 16; ++i) w3r[i] = w3g[i * 32 + lane];

    float c = 0.f;
    if (lane == 0) c = cell0[hid0 + w];
    __syncthreads();

    const uint2* p0 = (const uint2*)(wc + (size_t)(0 * 16 + w) * HID);
    const uint2* p1 = (const uint2*)(wc + (size_t)(1 * 16 + w) * HID);
    const uint2* p2 = (const uint2*)(wc + (size_t)(2 * 16 + w) * HID);
    const float4* h4 = (const float4*)h_sh;
    float4* h4s = (float4*)h_sh;

    for (int t = 0; t < TT; ++t) {
        // prefetch Zx for this step (independent of h)
        float zx0 = 0.f, zx1 = 0.f, zx2 = 0.f, zx3 = 0.f;
        if (lane == 0) {
            const float* zp = g_Zx + (size_t)t * NCOLS + hid0 + w;
            zx0 = zp[0];
            zx1 = zp[HID];
            zx2 = zp[2 * HID];
            zx3 = zp[3 * HID];
        }

        // stage h_{t-1} into SMEM (512 threads x 16B)
        const float4* hprev4 = (t == 0)
            ? (const float4*)hidden0
            : (const float4*)(g_hs + (size_t)(t - 1) * HID);
        h4s[tid] = hprev4[tid];
        __syncthreads();

        // matvec: 4 gate rows of unit w, all weights from SMEM/RF (no LDG)
        float a0 = 0.f, a1 = 0.f, a2 = 0.f, a3 = 0.f;
#pragma unroll
        for (int i = 0; i < 16; ++i) {
            int i4 = i * 32 + lane;
            float4 hv = h4[i4];                               // LDS.128
            uint2 q0 = p0[i4];                                // LDS.64 (4 halves)
            uint2 q1 = p1[i4];
            uint2 q2 = p2[i4];
            uint2 q3 = w3r[i];                                // regs
            float2 f0a = __half22float2(*(const __half2*)&q0.x);
            float2 f0b = __half22float2(*(const __half2*)&q0.y);
            float2 f1a = __half22float2(*(const __half2*)&q1.x);
            float2 f1b = __half22float2(*(const __half2*)&q1.y);
            float2 f2a = __half22float2(*(const __half2*)&q2.x);
            float2 f2b = __half22float2(*(const __half2*)&q2.y);
            float2 f3a = __half22float2(*(const __half2*)&q3.x);
            float2 f3b = __half22float2(*(const __half2*)&q3.y);
            a0 += f0a.x * hv.x + f0a.y * hv.y + f0b.x * hv.z + f0b.y * hv.w;
            a1 += f1a.x * hv.x + f1a.y * hv.y + f1b.x * hv.z + f1b.y * hv.w;
            a2 += f2a.x * hv.x + f2a.y * hv.y + f2b.x * hv.z + f2b.y * hv.w;
            a3 += f3a.x * hv.x + f3a.y * hv.y + f3b.x * hv.z + f3b.y * hv.w;
        }
#pragma unroll
        for (int off = 16; off; off >>= 1) {
            a0 += __shfl_down_sync(0xffffffffu, a0, off);
            a1 += __shfl_down_sync(0xffffffffu, a1, off);
            a2 += __shfl_down_sync(0xffffffffu, a2, off);
            a3 += __shfl_down_sync(0xffffffffu, a3, off);
        }

        // lane 0: gate math, cell update in register, store h
        if (lane == 0) {
            float zf = a0 + zx0;
            float zi = a1 + zx1;
            float zo = a2 + zx2;
            float zc = a3 + zx3;
            float f  = 1.0f / (1.0f + __expf(-zf));
            float i_ = 1.0f / (1.0f + __expf(-zi));
            float o_ = 1.0f / (1.0f + __expf(-zo));
            float gg = tanhf(zc);
            c = f * c + i_ * gg;
            float hn = o_ * tanhf(c);
            g_hs[(size_t)t * HID + hid0 + w] = hn;
            if (t == TT - 1) {
                dout[(size_t)TT * NCH + hid0 + w] = hn;          // h_fin
                dout[(size_t)TT * NCH + HID + hid0 + w] = c;     // c_fin
            }
        }
        __syncthreads();

        // grid barrier (128 CTAs co-resident, 1/SM)
        if (tid == 0) {
            asm volatile("red.release.gpu.global.add.u32 [%0], %1;"
                         :: "l"(&g_bar), "r"(1u) : "memory");
            unsigned target = (unsigned)(t + 1) * gridDim.x;
            while (ldacq(&g_bar) < target) { }
        }
        __syncthreads();
    }
}

// ---------------------------------------------------------------------------
// K3: out[t][n] = hs[t] @ Wout + bout.  M=4096, N=256, K=2048
// ---------------------------------------------------------------------------
__global__ __launch_bounds__(256) void out_gemm_kernel(
    const float* __restrict__ Wout, const float* __restrict__ bout,
    float* __restrict__ dout)
{
    __shared__ float As[64][17];
    __shared__ float Bs[16][64];

    int m0 = blockIdx.x * 64;
    int n0 = blockIdx.y * 64;
    int tid = threadIdx.x;
    int tx = tid & 15, ty = tid >> 4;

    float acc[4][4] = {};
    for (int k0 = 0; k0 < HID; k0 += 16) {
        {
            int kk = tid & 15;
            int mmb = tid >> 4;
#pragma unroll
            for (int r = 0; r < 4; ++r) {
                int mm = mmb + r * 16;
                As[mm][kk] = g_hs[(size_t)(m0 + mm) * HID + k0 + kk];
            }
        }
        {
            int nn = tid & 63;
            int kkb = tid >> 6;
#pragma unroll
            for (int r = 0; r < 4; ++r) {
                int kk = kkb + r * 4;
                Bs[kk][nn] = Wout[(size_t)(k0 + kk) * NCH + n0 + nn];
            }
        }
        __syncthreads();
#pragma unroll
        for (int kk = 0; kk < 16; ++kk) {
            float a[4];
#pragma unroll
            for (int i = 0; i < 4; ++i) a[i] = As[ty * 4 + i][kk];
            float4 bv = *(const float4*)&Bs[kk][tx * 4];
            float b[4] = {bv.x, bv.y, bv.z, bv.w};
#pragma unroll
            for (int i = 0; i < 4; ++i)
#pragma unroll
                for (int j = 0; j < 4; ++j) acc[i][j] += a[i] * b[j];
        }
        __syncthreads();
    }
#pragma unroll
    for (int i = 0; i < 4; ++i) {
        int m = m0 + ty * 4 + i;
#pragma unroll
        for (int j = 0; j < 4; ++j) {
            int n = n0 + tx * 4 + j;
            dout[(size_t)m * NCH + n] = acc[i][j] + bout[n];
        }
    }
}

// ---------------------------------------------------------------------------
extern "C" void kernel_launch(void* const* d_in, const int* in_sizes, int n_in,
                              void* d_out, int out_size)
{
    const int*   idx    = (const int*)d_in[0];
    const float* hidden = (const float*)d_in[1];
    const float* cell   = (const float*)d_in[2];
    const float* emb    = (const float*)d_in[3];
    const float* Wf     = (const float*)d_in[4];
    const float* bf     = (const float*)d_in[5];
    const float* Wi     = (const float*)d_in[6];
    const float* bi     = (const float*)d_in[7];
    const float* Wo     = (const float*)d_in[8];
    const float* bo     = (const float*)d_in[9];
    const float* Wc     = (const float*)d_in[10];
    const float* bc     = (const float*)d_in[11];
    const float* Wout   = (const float*)d_in[12];
    const float* bout   = (const float*)d_in[13];
    float* out = (float*)d_out;

    cudaFuncSetAttribute(lstm_seq_kernel,
                         cudaFuncAttributeMaxDynamicSharedMemorySize, SMEM_BYTES);

    bar_init_kernel<<<1, 1>>>();
    wt_transpose_kernel<<<dim3(64, 64, 4), 256>>>(Wf, Wi, Wo, Wc);
    zx_gemm_kernel<<<dim3(64, 128), 256>>>(idx, emb, Wf, Wi, Wo, Wc, bf, bi, bo, bc);
    lstm_seq_kernel<<<NCTA, THR, SMEM_BYTES>>>(hidden, cell, out);
    out_gemm_kernel<<<dim3(64, 4), 256>>>(Wout, bout, out);
}